// round 6
// baseline (speedup 1.0000x reference)
#include <cuda_runtime.h>

#define NNODES 50000
#define NEDGES 800000
#define FEAT   128
#define DROP_SCALE 2.5f   // 1/(1-0.6)

// ---------------- scratch (no allocations allowed) ----------------
__device__ float g_bufA[NNODES * FEAT];   // layer outputs h
__device__ float g_bufB[NNODES * FEAT];   // dropped activations z
__device__ float g_agg [NNODES * FEAT];   // neighborhood sums
__device__ int   g_deg [NNODES];
__device__ int   g_fill[NNODES];
__device__ int   g_rowptr[NNODES + 1];
__device__ int   g_col[NEDGES];
__device__ int   g_ei_is64;    // 1 if edge_index stored as int64
__device__ int   g_mask_kind;  // 0=uint8 bytes, 1=int32 words, 2=float32 words

// ---------------- dtype probe (deterministic, device-only) ----------------
__global__ void probe_kernel(const int* __restrict__ ei32,
                             const unsigned int* __restrict__ mask32) {
    if (threadIdx.x != 0 || blockIdx.x != 0) return;
    // edge_index: int64 node ids < 50000 => every odd 32-bit word is 0.
    int is64 = 1;
    for (int i = 1; i < 4096; i += 2) {
        if (ei32[i] != 0) { is64 = 0; break; }
    }
    g_ei_is64 = is64;
    // mask dtype probe on first 256 words
    bool allf = true, alli = true;
    for (int i = 0; i < 256; i++) {
        unsigned w = mask32[i];
        if (!(w == 0u || w == 0x3f800000u)) allf = false;
        if (!(w == 0u || w == 1u))          alli = false;
    }
    int kind = 0;
    if (alli) kind = 1;            // int32 0/1 (also catches all-zero prefix)
    else if (allf) kind = 2;       // float32 0.0/1.0
    g_mask_kind = kind;            // else uint8 bytes
}

// ---------------- CSR build ----------------
__global__ void zero_counts_kernel() {
    int i = blockIdx.x * blockDim.x + threadIdx.x;
    if (i < NNODES) { g_deg[i] = 0; g_fill[i] = 0; }
}

__device__ __forceinline__ int load_edge(const void* ei, int pos) {
    // pos in element units within the full [2, E] tensor
    if (g_ei_is64) {
        long long v = ((const long long*)ei)[pos];
        return (int)v;
    }
    return ((const int*)ei)[pos];
}

__global__ void hist_kernel(const void* __restrict__ ei) {
    int e = blockIdx.x * blockDim.x + threadIdx.x;
    if (e < NEDGES) {
        int d = load_edge(ei, NEDGES + e);     // dst row
        if ((unsigned)d < NNODES) atomicAdd(&g_deg[d], 1);
    }
}

__global__ void scan_kernel() {
    __shared__ int ssum[1024];
    const int t = threadIdx.x;
    const int CH = (NNODES + 1023) / 1024;
    int beg = t * CH;
    int end = beg + CH; if (end > NNODES) end = NNODES;
    int s = 0;
    for (int i = beg; i < end; i++) s += g_deg[i];
    ssum[t] = s;
    __syncthreads();
    for (int off = 1; off < 1024; off <<= 1) {
        int v = (t >= off) ? ssum[t - off] : 0;
        __syncthreads();
        ssum[t] += v;
        __syncthreads();
    }
    int run = (t == 0) ? 0 : ssum[t - 1];
    for (int i = beg; i < end; i++) { g_rowptr[i] = run; run += g_deg[i]; }
    if (t == 1023) g_rowptr[NNODES] = run;
}

__global__ void fill_kernel(const void* __restrict__ ei) {
    int e = blockIdx.x * blockDim.x + threadIdx.x;
    if (e < NEDGES) {
        int s = load_edge(ei, e);              // src row
        int d = load_edge(ei, NEDGES + e);     // dst row
        if ((unsigned)d < NNODES && (unsigned)s < NNODES) {
            int pos = g_rowptr[d] + atomicAdd(&g_fill[d], 1);
            g_col[pos] = s;
        }
    }
}

// ---------------- dropout (vectorized, dtype-adaptive mask) ----------------
// in == nullptr -> read from g_bufA.  Always writes g_bufB.
__global__ void dropout_kernel(const float* __restrict__ in,
                               const void* __restrict__ mask) {
    int i = blockIdx.x * blockDim.x + threadIdx.x;          // float4 index
    const int n4 = NNODES * FEAT / 4;
    if (i >= n4) return;
    const float* src = in ? in : g_bufA;
    float4 v = reinterpret_cast<const float4*>(src)[i];
    int keep0, keep1, keep2, keep3;
    int kind = g_mask_kind;
    if (kind == 0) {
        uchar4 m = reinterpret_cast<const uchar4*>(mask)[i];
        keep0 = m.x; keep1 = m.y; keep2 = m.z; keep3 = m.w;
    } else if (kind == 1) {
        int4 m = reinterpret_cast<const int4*>(mask)[i];
        keep0 = m.x; keep1 = m.y; keep2 = m.z; keep3 = m.w;
    } else {
        float4 m = reinterpret_cast<const float4*>(mask)[i];
        keep0 = (m.x != 0.f); keep1 = (m.y != 0.f);
        keep2 = (m.z != 0.f); keep3 = (m.w != 0.f);
    }
    float4 o;
    o.x = keep0 ? v.x * DROP_SCALE : 0.0f;
    o.y = keep1 ? v.y * DROP_SCALE : 0.0f;
    o.z = keep2 ? v.z * DROP_SCALE : 0.0f;
    o.w = keep3 ? v.w * DROP_SCALE : 0.0f;
    reinterpret_cast<float4*>(g_bufB)[i] = o;
}

// ---------------- gather aggregation: one warp per node ----------------
// Reads g_bufB, writes g_agg.
__global__ void aggregate_kernel() {
    int node = (blockIdx.x * blockDim.x + threadIdx.x) >> 5;
    int lane = threadIdx.x & 31;
    if (node >= NNODES) return;
    int beg = g_rowptr[node];
    int end = g_rowptr[node + 1];
    const float* z = g_bufB;
    float4 acc = make_float4(0.f, 0.f, 0.f, 0.f);
    int e = beg;
    for (; e + 2 <= end; e += 2) {
        int s0 = __ldg(&g_col[e]);
        int s1 = __ldg(&g_col[e + 1]);
        float4 v0 = __ldg(reinterpret_cast<const float4*>(z + (size_t)s0 * FEAT) + lane);
        float4 v1 = __ldg(reinterpret_cast<const float4*>(z + (size_t)s1 * FEAT) + lane);
        acc.x += v0.x + v1.x; acc.y += v0.y + v1.y;
        acc.z += v0.z + v1.z; acc.w += v0.w + v1.w;
    }
    if (e < end) {
        int s0 = __ldg(&g_col[e]);
        float4 v0 = __ldg(reinterpret_cast<const float4*>(z + (size_t)s0 * FEAT) + lane);
        acc.x += v0.x; acc.y += v0.y; acc.z += v0.z; acc.w += v0.w;
    }
    reinterpret_cast<float4*>(g_agg + (size_t)node * FEAT)[lane] = acc;
}

// ---------------- fused dual GEMM: C = agg@Wrel^T + z@Wroot^T + b (opt relu) ----
// A0 = g_agg, A1 = g_bufB (internal).  Cout == nullptr -> write g_bufA.
// BM=128, BN=128, BK=8, 256 threads, 8x8 per thread (4+4 split).
__global__ __launch_bounds__(256) void gemm_fused_kernel(
    const float* __restrict__ W0,   // W_rel [128,128] row-major
    const float* __restrict__ W1,   // W_root[128,128]
    const float* __restrict__ bias, // [128]
    float* __restrict__ Cout,       // external out or nullptr
    int doRelu) {
    __shared__ __align__(16) float As[8][128];
    __shared__ __align__(16) float Bs[8][128];

    const int row0 = blockIdx.x * 128;
    const int tid  = threadIdx.x;
    const int tx   = tid & 15;          // 0..15 -> output cols
    const int ty   = tid >> 4;          // 0..15 -> output rows

    const int lm = tid >> 1;            // A row within tile 0..127
    const int lk = (tid & 1) * 4;       // A k offset 0 or 4
    const int bo = tid & 127;           // B out-col 0..127
    const int bk = (tid >> 7) * 4;      // B k offset 0 or 4

    float acc[8][8];
#pragma unroll
    for (int i = 0; i < 8; i++)
#pragma unroll
        for (int j = 0; j < 8; j++) acc[i][j] = 0.f;

    for (int kb = 0; kb < 32; kb++) {
        const float* A = (kb < 16) ? g_agg : g_bufB;
        const float* W = (kb < 16) ? W0 : W1;
        const int k0 = (kb & 15) * 8;

        // load A tile (transposed into As[k][m])
        int r = row0 + lm;
        float4 av = make_float4(0.f, 0.f, 0.f, 0.f);
        if (r < NNODES)
            av = *reinterpret_cast<const float4*>(A + (size_t)r * FEAT + k0 + lk);
        As[lk + 0][lm] = av.x; As[lk + 1][lm] = av.y;
        As[lk + 2][lm] = av.z; As[lk + 3][lm] = av.w;

        // load B tile: Bs[k][o] = W[o][k]
        float4 bv = *reinterpret_cast<const float4*>(W + (size_t)bo * FEAT + k0 + bk);
        Bs[bk + 0][bo] = bv.x; Bs[bk + 1][bo] = bv.y;
        Bs[bk + 2][bo] = bv.z; Bs[bk + 3][bo] = bv.w;

        __syncthreads();

#pragma unroll
        for (int kk = 0; kk < 8; kk++) {
            float am[8], bn[8];
            float4 a0 = *reinterpret_cast<const float4*>(&As[kk][ty * 4]);
            float4 a1 = *reinterpret_cast<const float4*>(&As[kk][64 + ty * 4]);
            am[0] = a0.x; am[1] = a0.y; am[2] = a0.z; am[3] = a0.w;
            am[4] = a1.x; am[5] = a1.y; am[6] = a1.z; am[7] = a1.w;
            float4 b0 = *reinterpret_cast<const float4*>(&Bs[kk][tx * 4]);
            float4 b1 = *reinterpret_cast<const float4*>(&Bs[kk][64 + tx * 4]);
            bn[0] = b0.x; bn[1] = b0.y; bn[2] = b0.z; bn[3] = b0.w;
            bn[4] = b1.x; bn[5] = b1.y; bn[6] = b1.z; bn[7] = b1.w;
#pragma unroll
            for (int i = 0; i < 8; i++)
#pragma unroll
                for (int j = 0; j < 8; j++) acc[i][j] += am[i] * bn[j];
        }
        __syncthreads();
    }

    float* C = Cout ? Cout : g_bufA;

    // epilogue
#pragma unroll
    for (int i = 0; i < 8; i++) {
        int r = row0 + ((i < 4) ? (ty * 4 + i) : (64 + ty * 4 + i - 4));
        if (r >= NNODES) continue;
#pragma unroll
        for (int j = 0; j < 8; j++) {
            int c = (j < 4) ? (tx * 4 + j) : (64 + tx * 4 + j - 4);
            float v = acc[i][j] + __ldg(&bias[c]);
            if (doRelu) v = fmaxf(v, 0.f);
            C[(size_t)r * FEAT + c] = v;
        }
    }
}

// ---------------- launch (kernel launches ONLY — graph-capture safe) --------
extern "C" void kernel_launch(void* const* d_in, const int* in_sizes, int n_in,
                              void* d_out, int out_size) {
    const float* x      = (const float*)d_in[0];
    const void*  ei     = d_in[1];                 // int32 or int64 (probed)
    const float* Wrel0  = (const float*)d_in[2];
    const float* Wroot0 = (const float*)d_in[3];
    const float* b0     = (const float*)d_in[4];
    const float* Wrel1  = (const float*)d_in[5];
    const float* Wroot1 = (const float*)d_in[6];
    const float* b1     = (const float*)d_in[7];
    const float* Wrel2  = (const float*)d_in[8];
    const float* Wroot2 = (const float*)d_in[9];
    const float* b2     = (const float*)d_in[10];
    const void*  drop0  = d_in[11];                // uint8/int32/float32 (probed)
    const void*  drop1  = d_in[12];
    const void*  drop2  = d_in[13];

    float* out = (float*)d_out;

    const int TB = 256;
    const int nodeBlocks = (NNODES + TB - 1) / TB;
    const int edgeBlocks = (NEDGES + TB - 1) / TB;
    const int elemBlocks = (NNODES * FEAT / 4 + TB - 1) / TB;
    const int warpBlocks = (NNODES * 32 + TB - 1) / TB;
    const int gemmBlocks = (NNODES + 127) / 128;

    // dtype probe first (same stream => ordered before consumers)
    probe_kernel<<<1, 32>>>((const int*)ei, (const unsigned int*)drop0);

    // CSR build (deterministic structure; rebuilt every launch)
    zero_counts_kernel<<<nodeBlocks, TB>>>();
    hist_kernel<<<edgeBlocks, TB>>>(ei);
    scan_kernel<<<1, 1024>>>();
    fill_kernel<<<edgeBlocks, TB>>>(ei);

    // ---- layer 0 ----
    dropout_kernel<<<elemBlocks, TB>>>(x, drop0);
    aggregate_kernel<<<warpBlocks, TB>>>();
    gemm_fused_kernel<<<gemmBlocks, 256>>>(Wrel0, Wroot0, b0, nullptr, 1);

    // ---- layer 1 ----
    dropout_kernel<<<elemBlocks, TB>>>(nullptr, drop1);
    aggregate_kernel<<<warpBlocks, TB>>>();
    gemm_fused_kernel<<<gemmBlocks, 256>>>(Wrel1, Wroot1, b1, nullptr, 1);

    // ---- layer 2 ----
    dropout_kernel<<<elemBlocks, TB>>>(nullptr, drop2);
    aggregate_kernel<<<warpBlocks, TB>>>();
    gemm_fused_kernel<<<gemmBlocks, 256>>>(Wrel2, Wroot2, b2, out, 0);
}

// round 8
// speedup vs baseline: 1.9544x; 1.9544x over previous
#include <cuda_runtime.h>

#define NNODES 50000
#define NEDGES 800000
#define FEAT   128
#define DROP_SCALE 2.5f   // 1/(1-0.6)
#define NCHUNK ((NNODES + 255) / 256)   // 196

// ---------------- scratch (no allocations allowed) ----------------
__device__ float g_bufB[NNODES * FEAT];   // dropped activations z (in-place per layer)
__device__ float g_agg [NNODES * FEAT];   // neighborhood sums
__device__ int   g_deg [NNODES];
__device__ int   g_fill[NNODES];
__device__ int   g_rowptr[NNODES + 1];
__device__ int   g_col[NEDGES];
__device__ int   g_chunksum[256];
__device__ int   g_ei_is64;    // 1 if edge_index stored as int64
__device__ int   g_mask_kind;  // 0=uint8 bytes, 1=int32 words, 2=float32 words

// ---------------- dtype probe (deterministic, device-only) ----------------
__global__ void probe_kernel(const int* __restrict__ ei32,
                             const unsigned int* __restrict__ mask32) {
    if (threadIdx.x != 0 || blockIdx.x != 0) return;
    int is64 = 1;
    for (int i = 1; i < 4096; i += 2) {
        if (ei32[i] != 0) { is64 = 0; break; }
    }
    g_ei_is64 = is64;
    bool allf = true, alli = true;
    for (int i = 0; i < 256; i++) {
        unsigned w = mask32[i];
        if (!(w == 0u || w == 0x3f800000u)) allf = false;
        if (!(w == 0u || w == 1u))          alli = false;
    }
    int kind = 0;
    if (alli) kind = 1;
    else if (allf) kind = 2;
    g_mask_kind = kind;
}

// ---------------- CSR build ----------------
__global__ void zero_counts_kernel() {
    int i = blockIdx.x * blockDim.x + threadIdx.x;
    if (i < NNODES) { g_deg[i] = 0; g_fill[i] = 0; }
}

__device__ __forceinline__ int load_edge(const void* ei, int pos) {
    if (g_ei_is64) return (int)((const long long*)ei)[pos];
    return ((const int*)ei)[pos];
}

__global__ void hist_kernel(const void* __restrict__ ei) {
    int e = blockIdx.x * blockDim.x + threadIdx.x;
    if (e < NEDGES) {
        int d = load_edge(ei, NEDGES + e);
        if ((unsigned)d < NNODES) atomicAdd(&g_deg[d], 1);
    }
}

// ---- multi-block exclusive scan of g_deg -> g_rowptr (3 fast kernels) ----
__global__ void chunk_sum_kernel() {   // NCHUNK blocks x 256
    __shared__ int sh[256];
    int t = threadIdx.x;
    int i = blockIdx.x * 256 + t;
    int v = (i < NNODES) ? g_deg[i] : 0;
    sh[t] = v; __syncthreads();
#pragma unroll
    for (int off = 128; off > 0; off >>= 1) {
        if (t < off) sh[t] += sh[t + off];
        __syncthreads();
    }
    if (t == 0) g_chunksum[blockIdx.x] = sh[0];
}

__global__ void chunk_scan_kernel() {  // 1 block x 256 (tiny)
    __shared__ int sh[256];
    int t = threadIdx.x;
    int v = (t < NCHUNK) ? g_chunksum[t] : 0;
    sh[t] = v; __syncthreads();
#pragma unroll
    for (int off = 1; off < 256; off <<= 1) {
        int u = (t >= off) ? sh[t - off] : 0;
        __syncthreads();
        sh[t] += u;
        __syncthreads();
    }
    g_chunksum[t] = sh[t] - v;   // exclusive
}

__global__ void rowptr_kernel() {      // NCHUNK blocks x 256
    __shared__ int sh[256];
    int t = threadIdx.x;
    int i = blockIdx.x * 256 + t;
    int v = (i < NNODES) ? g_deg[i] : 0;
    sh[t] = v; __syncthreads();
#pragma unroll
    for (int off = 1; off < 256; off <<= 1) {
        int u = (t >= off) ? sh[t - off] : 0;
        __syncthreads();
        sh[t] += u;
        __syncthreads();
    }
    int excl = sh[t] - v + g_chunksum[blockIdx.x];
    if (i < NNODES) g_rowptr[i] = excl;
    if (i == NNODES - 1) g_rowptr[NNODES] = excl + v;
}

__global__ void fill_kernel(const void* __restrict__ ei) {
    int e = blockIdx.x * blockDim.x + threadIdx.x;
    if (e < NEDGES) {
        int s = load_edge(ei, e);
        int d = load_edge(ei, NEDGES + e);
        if ((unsigned)d < NNODES && (unsigned)s < NNODES) {
            int pos = g_rowptr[d] + atomicAdd(&g_fill[d], 1);
            g_col[pos] = s;
        }
    }
}

// ---------------- layer-0 dropout (x -> g_bufB) ----------------
__global__ void dropout_kernel(const float* __restrict__ in,
                               const void* __restrict__ mask) {
    int i = blockIdx.x * blockDim.x + threadIdx.x;
    const int n4 = NNODES * FEAT / 4;
    if (i >= n4) return;
    float4 v = reinterpret_cast<const float4*>(in)[i];
    int k0, k1, k2, k3;
    int kind = g_mask_kind;
    if (kind == 0) {
        uchar4 m = reinterpret_cast<const uchar4*>(mask)[i];
        k0 = m.x; k1 = m.y; k2 = m.z; k3 = m.w;
    } else if (kind == 1) {
        int4 m = reinterpret_cast<const int4*>(mask)[i];
        k0 = m.x; k1 = m.y; k2 = m.z; k3 = m.w;
    } else {
        float4 m = reinterpret_cast<const float4*>(mask)[i];
        k0 = (m.x != 0.f); k1 = (m.y != 0.f); k2 = (m.z != 0.f); k3 = (m.w != 0.f);
    }
    float4 o;
    o.x = k0 ? v.x * DROP_SCALE : 0.0f;
    o.y = k1 ? v.y * DROP_SCALE : 0.0f;
    o.z = k2 ? v.z * DROP_SCALE : 0.0f;
    o.w = k3 ? v.w * DROP_SCALE : 0.0f;
    reinterpret_cast<float4*>(g_bufB)[i] = o;
}

// ---------------- gather aggregation: one warp per node ----------------
__global__ void aggregate_kernel() {
    int node = (blockIdx.x * blockDim.x + threadIdx.x) >> 5;
    int lane = threadIdx.x & 31;
    if (node >= NNODES) return;
    int beg = g_rowptr[node];
    int end = g_rowptr[node + 1];
    const float* z = g_bufB;
    float4 acc = make_float4(0.f, 0.f, 0.f, 0.f);
    int e = beg;
    for (; e + 2 <= end; e += 2) {
        int s0 = __ldg(&g_col[e]);
        int s1 = __ldg(&g_col[e + 1]);
        float4 v0 = __ldg(reinterpret_cast<const float4*>(z + (size_t)s0 * FEAT) + lane);
        float4 v1 = __ldg(reinterpret_cast<const float4*>(z + (size_t)s1 * FEAT) + lane);
        acc.x += v0.x + v1.x; acc.y += v0.y + v1.y;
        acc.z += v0.z + v1.z; acc.w += v0.w + v1.w;
    }
    if (e < end) {
        int s0 = __ldg(&g_col[e]);
        float4 v0 = __ldg(reinterpret_cast<const float4*>(z + (size_t)s0 * FEAT) + lane);
        acc.x += v0.x; acc.y += v0.y; acc.z += v0.z; acc.w += v0.w;
    }
    reinterpret_cast<float4*>(g_agg + (size_t)node * FEAT)[lane] = acc;
}

// ---- fused dual GEMM + relu + NEXT-layer dropout -------------------------
// C = g_agg@W0^T + g_bufB@W1^T + b;  relu optional.
// nextMask != nullptr: apply dropout, write z into g_bufB IN PLACE
//   (safe: each block reads only its own 128 rows, then writes the same rows).
// nextMask == nullptr: write raw result to Cout (final layer).
__global__ __launch_bounds__(256) void gemm_fused_kernel(
    const float* __restrict__ W0,
    const float* __restrict__ W1,
    const float* __restrict__ bias,
    const void*  __restrict__ nextMask,
    float* __restrict__ Cout,
    int doRelu) {
    __shared__ __align__(16) float As[8][128];
    __shared__ __align__(16) float Bs[8][128];

    const int row0 = blockIdx.x * 128;
    const int tid  = threadIdx.x;
    const int tx   = tid & 15;
    const int ty   = tid >> 4;

    const int lm = tid >> 1;            // A row within tile 0..127
    const int lk = (tid & 1) * 4;       // A k offset 0 or 4
    const int bo = tid & 127;           // B out-col 0..127
    const int bk = (tid >> 7) * 4;      // B k offset 0 or 4

    float acc[8][8];
#pragma unroll
    for (int i = 0; i < 8; i++)
#pragma unroll
        for (int j = 0; j < 8; j++) acc[i][j] = 0.f;

    const int rA = row0 + lm;
    const bool rAok = (rA < NNODES);

    // prefetch tile kb=0
    float4 av, bv;
    {
        av = make_float4(0.f, 0.f, 0.f, 0.f);
        if (rAok) av = *reinterpret_cast<const float4*>(g_agg + (size_t)rA * FEAT + 0 + lk);
        bv = *reinterpret_cast<const float4*>(W0 + (size_t)bo * FEAT + 0 + bk);
    }

    for (int kb = 0; kb < 32; kb++) {
        // store prefetched tile to smem
        As[lk + 0][lm] = av.x; As[lk + 1][lm] = av.y;
        As[lk + 2][lm] = av.z; As[lk + 3][lm] = av.w;
        Bs[bk + 0][bo] = bv.x; Bs[bk + 1][bo] = bv.y;
        Bs[bk + 2][bo] = bv.z; Bs[bk + 3][bo] = bv.w;
        __syncthreads();

        // prefetch next tile (overlaps with compute below)
        if (kb + 1 < 32) {
            int kb2 = kb + 1;
            const float* A = (kb2 < 16) ? g_agg : g_bufB;
            const float* W = (kb2 < 16) ? W0 : W1;
            const int k0 = (kb2 & 15) * 8;
            av = make_float4(0.f, 0.f, 0.f, 0.f);
            if (rAok) av = *reinterpret_cast<const float4*>(A + (size_t)rA * FEAT + k0 + lk);
            bv = *reinterpret_cast<const float4*>(W + (size_t)bo * FEAT + k0 + bk);
        }

#pragma unroll
        for (int kk = 0; kk < 8; kk++) {
            float am[8], bn[8];
            float4 a0 = *reinterpret_cast<const float4*>(&As[kk][ty * 4]);
            float4 a1 = *reinterpret_cast<const float4*>(&As[kk][64 + ty * 4]);
            am[0] = a0.x; am[1] = a0.y; am[2] = a0.z; am[3] = a0.w;
            am[4] = a1.x; am[5] = a1.y; am[6] = a1.z; am[7] = a1.w;
            float4 b0 = *reinterpret_cast<const float4*>(&Bs[kk][tx * 4]);
            float4 b1 = *reinterpret_cast<const float4*>(&Bs[kk][64 + tx * 4]);
            bn[0] = b0.x; bn[1] = b0.y; bn[2] = b0.z; bn[3] = b0.w;
            bn[4] = b1.x; bn[5] = b1.y; bn[6] = b1.z; bn[7] = b1.w;
#pragma unroll
            for (int i = 0; i < 8; i++)
#pragma unroll
                for (int j = 0; j < 8; j++) acc[i][j] += am[i] * bn[j];
        }
        __syncthreads();
    }

    const int kind = g_mask_kind;
    float* C = nextMask ? g_bufB : Cout;

#pragma unroll
    for (int i = 0; i < 8; i++) {
        int r = row0 + ((i < 4) ? (ty * 4 + i) : (64 + ty * 4 + i - 4));
        if (r >= NNODES) continue;
#pragma unroll
        for (int j = 0; j < 8; j++) {
            int c = (j < 4) ? (tx * 4 + j) : (64 + tx * 4 + j - 4);
            float v = acc[i][j] + __ldg(&bias[c]);
            if (doRelu) v = fmaxf(v, 0.f);
            if (nextMask) {
                size_t idx = (size_t)r * FEAT + c;
                int keep;
                if (kind == 0)      keep = ((const unsigned char*)nextMask)[idx];
                else if (kind == 1) keep = ((const int*)nextMask)[idx];
                else                keep = (((const float*)nextMask)[idx] != 0.f);
                v = keep ? v * DROP_SCALE : 0.0f;
            }
            C[(size_t)r * FEAT + c] = v;
        }
    }
}

// ---------------- launch (kernel launches ONLY — graph-capture safe) --------
extern "C" void kernel_launch(void* const* d_in, const int* in_sizes, int n_in,
                              void* d_out, int out_size) {
    const float* x      = (const float*)d_in[0];
    const void*  ei     = d_in[1];
    const float* Wrel0  = (const float*)d_in[2];
    const float* Wroot0 = (const float*)d_in[3];
    const float* b0     = (const float*)d_in[4];
    const float* Wrel1  = (const float*)d_in[5];
    const float* Wroot1 = (const float*)d_in[6];
    const float* b1     = (const float*)d_in[7];
    const float* Wrel2  = (const float*)d_in[8];
    const float* Wroot2 = (const float*)d_in[9];
    const float* b2     = (const float*)d_in[10];
    const void*  drop0  = d_in[11];
    const void*  drop1  = d_in[12];
    const void*  drop2  = d_in[13];

    float* out = (float*)d_out;

    const int TB = 256;
    const int nodeBlocks = (NNODES + TB - 1) / TB;
    const int edgeBlocks = (NEDGES + TB - 1) / TB;
    const int elemBlocks = (NNODES * FEAT / 4 + TB - 1) / TB;
    const int warpBlocks = (NNODES * 32 + TB - 1) / TB;
    const int gemmBlocks = (NNODES + 127) / 128;

    probe_kernel<<<1, 32>>>((const int*)ei, (const unsigned int*)drop0);

    // CSR build (deterministic; rebuilt every launch)
    zero_counts_kernel<<<nodeBlocks, TB>>>();
    hist_kernel<<<edgeBlocks, TB>>>(ei);
    chunk_sum_kernel<<<NCHUNK, 256>>>();
    chunk_scan_kernel<<<1, 256>>>();
    rowptr_kernel<<<NCHUNK, 256>>>();
    fill_kernel<<<edgeBlocks, TB>>>(ei);

    // ---- layer 0 ----
    dropout_kernel<<<elemBlocks, TB>>>(x, drop0);
    aggregate_kernel<<<warpBlocks, TB>>>();
    gemm_fused_kernel<<<gemmBlocks, 256>>>(Wrel0, Wroot0, b0, drop1, nullptr, 1);

    // ---- layer 1 (z1 already in g_bufB) ----
    aggregate_kernel<<<warpBlocks, TB>>>();
    gemm_fused_kernel<<<gemmBlocks, 256>>>(Wrel1, Wroot1, b1, drop2, nullptr, 1);

    // ---- layer 2 ----
    aggregate_kernel<<<warpBlocks, TB>>>();
    gemm_fused_kernel<<<gemmBlocks, 256>>>(Wrel2, Wroot2, b2, nullptr, out, 0);
}

// round 12
// speedup vs baseline: 3.0880x; 1.5801x over previous
#include <cuda_runtime.h>
#include <cuda_bf16.h>
#include <cstdint>

#define NNODES 50000
#define NEDGES 800000
#define FEAT   128
#define DROP_SCALE 2.5f   // 1/(1-0.6)
#define NCHUNK ((NNODES + 255) / 256)   // 196

// ---------------- scratch (no allocations allowed) ----------------
__device__ float    g_bufB[NNODES * FEAT];   // dropped activations z
__device__ float    g_agg [NNODES * FEAT];   // neighborhood sums
__device__ int      g_deg [NNODES];
__device__ int      g_fill[NNODES];
__device__ int      g_rowptr[NNODES + 1];
__device__ int      g_col[NEDGES];
__device__ int      g_chunksum[256];
__device__ int      g_ei_is64;
__device__ int      g_mask_kind;   // 0=uint8, 1=int32, 2=float32
__device__ uint32_t g_Whi[2][128 * 64];  // pre-split weights, bf16x2 pairs [n][kpair]
__device__ uint32_t g_Wlo[2][128 * 64];

// ---------------- bf16 split helpers ----------------
__device__ __forceinline__ void split_pair(float x, float y, uint32_t& hi, uint32_t& lo) {
    __nv_bfloat16 hx = __float2bfloat16_rn(x);
    __nv_bfloat16 hy = __float2bfloat16_rn(y);
    float rx = x - __bfloat162float(hx);
    float ry = y - __bfloat162float(hy);
    __nv_bfloat16 lx = __float2bfloat16_rn(rx);
    __nv_bfloat16 ly = __float2bfloat16_rn(ry);
    hi = ((uint32_t)__bfloat16_as_ushort(hy) << 16) | (uint32_t)__bfloat16_as_ushort(hx);
    lo = ((uint32_t)__bfloat16_as_ushort(ly) << 16) | (uint32_t)__bfloat16_as_ushort(lx);
}

#define MMA_BF16(d, a, bv0, bv1) \
    asm volatile("mma.sync.aligned.m16n8k16.row.col.f32.bf16.bf16.f32 " \
        "{%0,%1,%2,%3}, {%4,%5,%6,%7}, {%8,%9}, {%0,%1,%2,%3};" \
        : "+f"((d)[0]), "+f"((d)[1]), "+f"((d)[2]), "+f"((d)[3]) \
        : "r"((a)[0]), "r"((a)[1]), "r"((a)[2]), "r"((a)[3]), "r"(bv0), "r"(bv1))

// ---------------- dtype probe ----------------
__global__ void probe_kernel(const int* __restrict__ ei32,
                             const unsigned int* __restrict__ mask32) {
    if (threadIdx.x != 0 || blockIdx.x != 0) return;
    int is64 = 1;
    for (int i = 1; i < 4096; i += 2) {
        if (ei32[i] != 0) { is64 = 0; break; }
    }
    g_ei_is64 = is64;
    bool allf = true, alli = true;
    for (int i = 0; i < 256; i++) {
        unsigned w = mask32[i];
        if (!(w == 0u || w == 0x3f800000u)) allf = false;
        if (!(w == 0u || w == 1u))          alli = false;
    }
    int kind = 0;
    if (alli) kind = 1;
    else if (allf) kind = 2;
    g_mask_kind = kind;
}

// ---------------- CSR build ----------------
__global__ void zero_counts_kernel() {
    int i = blockIdx.x * blockDim.x + threadIdx.x;
    if (i < NNODES) { g_deg[i] = 0; g_fill[i] = 0; }
}

__device__ __forceinline__ int load_edge(const void* ei, int pos) {
    if (g_ei_is64) return (int)((const long long*)ei)[pos];
    return ((const int*)ei)[pos];
}

__global__ void hist_kernel(const void* __restrict__ ei) {
    int e = blockIdx.x * blockDim.x + threadIdx.x;
    if (e < NEDGES) {
        int d = load_edge(ei, NEDGES + e);
        if ((unsigned)d < NNODES) atomicAdd(&g_deg[d], 1);
    }
}

__global__ void chunk_sum_kernel() {
    __shared__ int sh[256];
    int t = threadIdx.x;
    int i = blockIdx.x * 256 + t;
    int v = (i < NNODES) ? g_deg[i] : 0;
    sh[t] = v; __syncthreads();
#pragma unroll
    for (int off = 128; off > 0; off >>= 1) {
        if (t < off) sh[t] += sh[t + off];
        __syncthreads();
    }
    if (t == 0) g_chunksum[blockIdx.x] = sh[0];
}

__global__ void chunk_scan_kernel() {
    __shared__ int sh[256];
    int t = threadIdx.x;
    int v = (t < NCHUNK) ? g_chunksum[t] : 0;
    sh[t] = v; __syncthreads();
#pragma unroll
    for (int off = 1; off < 256; off <<= 1) {
        int u = (t >= off) ? sh[t - off] : 0;
        __syncthreads();
        sh[t] += u;
        __syncthreads();
    }
    g_chunksum[t] = sh[t] - v;
}

__global__ void rowptr_kernel() {
    __shared__ int sh[256];
    int t = threadIdx.x;
    int i = blockIdx.x * 256 + t;
    int v = (i < NNODES) ? g_deg[i] : 0;
    sh[t] = v; __syncthreads();
#pragma unroll
    for (int off = 1; off < 256; off <<= 1) {
        int u = (t >= off) ? sh[t - off] : 0;
        __syncthreads();
        sh[t] += u;
        __syncthreads();
    }
    int excl = sh[t] - v + g_chunksum[blockIdx.x];
    if (i < NNODES) g_rowptr[i] = excl;
    if (i == NNODES - 1) g_rowptr[NNODES] = excl + v;
}

__global__ void fill_kernel(const void* __restrict__ ei) {
    int e = blockIdx.x * blockDim.x + threadIdx.x;
    if (e < NEDGES) {
        int s = load_edge(ei, e);
        int d = load_edge(ei, NEDGES + e);
        if ((unsigned)d < NNODES && (unsigned)s < NNODES) {
            int pos = g_rowptr[d] + atomicAdd(&g_fill[d], 1);
            g_col[pos] = s;
        }
    }
}

// ---------------- layer-0 dropout (x -> g_bufB) ----------------
__global__ void dropout_kernel(const float* __restrict__ in,
                               const void* __restrict__ mask) {
    int i = blockIdx.x * blockDim.x + threadIdx.x;
    const int n4 = NNODES * FEAT / 4;
    if (i >= n4) return;
    float4 v = reinterpret_cast<const float4*>(in)[i];
    int k0, k1, k2, k3;
    int kind = g_mask_kind;
    if (kind == 0) {
        uchar4 m = reinterpret_cast<const uchar4*>(mask)[i];
        k0 = m.x; k1 = m.y; k2 = m.z; k3 = m.w;
    } else if (kind == 1) {
        int4 m = reinterpret_cast<const int4*>(mask)[i];
        k0 = m.x; k1 = m.y; k2 = m.z; k3 = m.w;
    } else {
        float4 m = reinterpret_cast<const float4*>(mask)[i];
        k0 = (m.x != 0.f); k1 = (m.y != 0.f); k2 = (m.z != 0.f); k3 = (m.w != 0.f);
    }
    float4 o;
    o.x = k0 ? v.x * DROP_SCALE : 0.0f;
    o.y = k1 ? v.y * DROP_SCALE : 0.0f;
    o.z = k2 ? v.z * DROP_SCALE : 0.0f;
    o.w = k3 ? v.w * DROP_SCALE : 0.0f;
    reinterpret_cast<float4*>(g_bufB)[i] = o;
}

// ---------------- gather aggregation: one warp per node ----------------
__global__ void aggregate_kernel() {
    int node = (blockIdx.x * blockDim.x + threadIdx.x) >> 5;
    int lane = threadIdx.x & 31;
    if (node >= NNODES) return;
    int beg = g_rowptr[node];
    int end = g_rowptr[node + 1];
    const float* z = g_bufB;
    float4 acc = make_float4(0.f, 0.f, 0.f, 0.f);
    int e = beg;
    for (; e + 2 <= end; e += 2) {
        int s0 = __ldg(&g_col[e]);
        int s1 = __ldg(&g_col[e + 1]);
        float4 v0 = __ldg(reinterpret_cast<const float4*>(z + (size_t)s0 * FEAT) + lane);
        float4 v1 = __ldg(reinterpret_cast<const float4*>(z + (size_t)s1 * FEAT) + lane);
        acc.x += v0.x + v1.x; acc.y += v0.y + v1.y;
        acc.z += v0.z + v1.z; acc.w += v0.w + v1.w;
    }
    if (e < end) {
        int s0 = __ldg(&g_col[e]);
        float4 v0 = __ldg(reinterpret_cast<const float4*>(z + (size_t)s0 * FEAT) + lane);
        acc.x += v0.x; acc.y += v0.y; acc.z += v0.z; acc.w += v0.w;
    }
    reinterpret_cast<float4*>(g_agg + (size_t)node * FEAT)[lane] = acc;
}

// ---------------- weight pre-split: fp32 [n][k] -> bf16x2 hi/lo [n][kpair] ----
__global__ void wsplit_kernel(const float* __restrict__ W0,
                              const float* __restrict__ W1) {
    int i = blockIdx.x * blockDim.x + threadIdx.x;   // pair index
    if (i >= 128 * 64) return;
    float2 a = *reinterpret_cast<const float2*>(W0 + 2 * i);
    float2 b = *reinterpret_cast<const float2*>(W1 + 2 * i);
    split_pair(a.x, a.y, g_Whi[0][i], g_Wlo[0][i]);
    split_pair(b.x, b.y, g_Whi[1][i], g_Wlo[1][i]);
}

// ================= mma.sync bf16 2-split dual GEMM =================
// C[128,128] = [agg|z](128x256) @ [W0|W1]^T + bias, via m16n8k16 bf16 HMMA,
// 3 products (AhBh + AlBh + AhBl), fp32 accumulation in registers.
// SMEM: bf16x2 pair tiles, pairs (p, p+4) adjacent (interleave), XOR-quad
// swizzle -> conflict-free LDS.64 frag reads and STS.128 writes. 32KB static.
__global__ __launch_bounds__(256, 2) void gemm_mma_kernel(
    const float* __restrict__ bias,
    const void*  __restrict__ nextMask,
    float* __restrict__ Cout,
    int doRelu) {
    __shared__ uint32_t sAh[128 * 16];
    __shared__ uint32_t sAl[128 * 16];
    __shared__ uint32_t sBh[128 * 16];
    __shared__ uint32_t sBl[128 * 16];

    const int tid  = threadIdx.x;
    const int warp = tid >> 5;
    const int lane = tid & 31;
    const int wm   = warp & 3;          // 4 warps along M (32 rows each)
    const int wn   = warp >> 2;         // 2 warps along N (64 cols each)
    const int row0 = blockIdx.x * 128;

    float acc[2][8][4];
#pragma unroll
    for (int a = 0; a < 2; a++)
#pragma unroll
        for (int b = 0; b < 8; b++)
#pragma unroll
            for (int c = 0; c < 4; c++) acc[a][b][c] = 0.f;

    for (int ch = 0; ch < 8; ch++) {
        const float* Aptr = (ch < 4) ? g_agg : g_bufB;
        const uint32_t* Whp = g_Whi[(ch < 4) ? 0 : 1];
        const uint32_t* Wlp = g_Wlo[(ch < 4) ? 0 : 1];
        const int k0  = (ch & 3) * 32;   // element base within 128
        const int kp0 = (ch & 3) * 16;   // pair base within 64

        // ---- A tile: 512 units, 2 per thread ----
#pragma unroll
        for (int jj = 0; jj < 2; jj++) {
            int u = tid + 256 * jj;
            int r = u >> 2, g = (u >> 1) & 1, h = u & 1;
            int kbase = k0 + (g * 8 + 2 * h) * 2;
            int gr = row0 + r;
            float4 va = make_float4(0.f, 0.f, 0.f, 0.f), vb = va;
            if (gr < NNODES) {
                const float* rp = Aptr + (size_t)gr * FEAT + kbase;
                va = *reinterpret_cast<const float4*>(rp);
                vb = *reinterpret_cast<const float4*>(rp + 8);
            }
            uint32_t ha0, la0, ha1, la1, hb0, lb0, hb1, lb1;
            split_pair(va.x, va.y, ha0, la0);
            split_pair(va.z, va.w, ha1, la1);
            split_pair(vb.x, vb.y, hb0, lb0);
            split_pair(vb.z, vb.w, hb1, lb1);
            int waddr = r * 16 + ((g * 8 + 4 * h) ^ ((r & 3) << 2));
            *reinterpret_cast<uint4*>(&sAh[waddr]) = make_uint4(ha0, hb0, ha1, hb1);
            *reinterpret_cast<uint4*>(&sAl[waddr]) = make_uint4(la0, lb0, la1, lb1);
        }
        // ---- B tile (pre-split weights): 512 units, 2 per thread ----
#pragma unroll
        for (int jj = 0; jj < 2; jj++) {
            int u = tid + 256 * jj;
            int n = u >> 2, g = (u >> 1) & 1, h = u & 1;
            int kp = kp0 + g * 8 + 2 * h;
            const uint32_t* sh_ = Whp + n * 64 + kp;
            const uint32_t* sl_ = Wlp + n * 64 + kp;
            uint2 hA = *reinterpret_cast<const uint2*>(sh_);
            uint2 hB = *reinterpret_cast<const uint2*>(sh_ + 4);
            uint2 lA = *reinterpret_cast<const uint2*>(sl_);
            uint2 lB = *reinterpret_cast<const uint2*>(sl_ + 4);
            int waddr = n * 16 + ((g * 8 + 4 * h) ^ ((n & 3) << 2));
            *reinterpret_cast<uint4*>(&sBh[waddr]) = make_uint4(hA.x, hB.x, hA.y, hB.y);
            *reinterpret_cast<uint4*>(&sBl[waddr]) = make_uint4(lA.x, lB.x, lA.y, lB.y);
        }
        __syncthreads();

#pragma unroll
        for (int ks = 0; ks < 2; ks++) {
            const int q = ks * 8 + 2 * (lane & 3);
            uint32_t Ah[2][4], Al[2][4];
#pragma unroll
            for (int mt = 0; mt < 2; mt++) {
                int r = wm * 32 + mt * 16 + (lane >> 2);
                int w0 = r * 16 + (q ^ ((r & 3) << 2));
                int w1 = w0 + 8 * 16;    // row r+8: same swizzle ((r+8)&3 == r&3)
                uint2 t0 = *reinterpret_cast<const uint2*>(&sAh[w0]);
                uint2 t1 = *reinterpret_cast<const uint2*>(&sAh[w1]);
                Ah[mt][0] = t0.x; Ah[mt][1] = t1.x; Ah[mt][2] = t0.y; Ah[mt][3] = t1.y;
                uint2 u0 = *reinterpret_cast<const uint2*>(&sAl[w0]);
                uint2 u1 = *reinterpret_cast<const uint2*>(&sAl[w1]);
                Al[mt][0] = u0.x; Al[mt][1] = u1.x; Al[mt][2] = u0.y; Al[mt][3] = u1.y;
            }
#pragma unroll
            for (int nt = 0; nt < 8; nt++) {
                int n = wn * 64 + nt * 8 + (lane >> 2);
                int w = n * 16 + (q ^ ((n & 3) << 2));
                uint2 bh = *reinterpret_cast<const uint2*>(&sBh[w]);
                uint2 bl = *reinterpret_cast<const uint2*>(&sBl[w]);
#pragma unroll
                for (int mt = 0; mt < 2; mt++) {
                    MMA_BF16(acc[mt][nt], Ah[mt], bh.x, bh.y);
                    MMA_BF16(acc[mt][nt], Al[mt], bh.x, bh.y);
                    MMA_BF16(acc[mt][nt], Ah[mt], bl.x, bl.y);
                }
            }
        }
        __syncthreads();
    }

    // ---- epilogue: bias + relu + next-layer dropout, frag -> global ----
    const int kind = g_mask_kind;
    float* C = nextMask ? g_bufB : Cout;

    float2 biasv[8];
#pragma unroll
    for (int nt = 0; nt < 8; nt++) {
        int col = wn * 64 + nt * 8 + 2 * (lane & 3);
        biasv[nt] = *reinterpret_cast<const float2*>(bias + col);
    }

#pragma unroll
    for (int mt = 0; mt < 2; mt++) {
        int rbase = row0 + wm * 32 + mt * 16 + (lane >> 2);
#pragma unroll
        for (int half = 0; half < 2; half++) {
            int row = rbase + 8 * half;
            if (row >= NNODES) continue;
#pragma unroll
            for (int nt = 0; nt < 8; nt++) {
                int col = wn * 64 + nt * 8 + 2 * (lane & 3);
                float v0 = acc[mt][nt][2 * half + 0] + biasv[nt].x;
                float v1 = acc[mt][nt][2 * half + 1] + biasv[nt].y;
                if (doRelu) { v0 = fmaxf(v0, 0.f); v1 = fmaxf(v1, 0.f); }
                if (nextMask) {
                    size_t ib = (size_t)row * FEAT + col;
                    int m0, m1;
                    if (kind == 0) {
                        const unsigned char* m = (const unsigned char*)nextMask;
                        m0 = m[ib]; m1 = m[ib + 1];
                    } else if (kind == 1) {
                        const int* m = (const int*)nextMask;
                        m0 = m[ib]; m1 = m[ib + 1];
                    } else {
                        const float* m = (const float*)nextMask;
                        m0 = (m[ib] != 0.f); m1 = (m[ib + 1] != 0.f);
                    }
                    v0 = m0 ? v0 * DROP_SCALE : 0.f;
                    v1 = m1 ? v1 * DROP_SCALE : 0.f;
                }
                *reinterpret_cast<float2*>(C + (size_t)row * FEAT + col) = make_float2(v0, v1);
            }
        }
    }
}

// ---------------- launch (kernel launches ONLY — graph-capture safe) --------
extern "C" void kernel_launch(void* const* d_in, const int* in_sizes, int n_in,
                              void* d_out, int out_size) {
    const float* x      = (const float*)d_in[0];
    const void*  ei     = d_in[1];
    const float* Wrel0  = (const float*)d_in[2];
    const float* Wroot0 = (const float*)d_in[3];
    const float* b0     = (const float*)d_in[4];
    const float* Wrel1  = (const float*)d_in[5];
    const float* Wroot1 = (const float*)d_in[6];
    const float* b1     = (const float*)d_in[7];
    const float* Wrel2  = (const float*)d_in[8];
    const float* Wroot2 = (const float*)d_in[9];
    const float* b2     = (const float*)d_in[10];
    const void*  drop0  = d_in[11];
    const void*  drop1  = d_in[12];
    const void*  drop2  = d_in[13];

    float* out = (float*)d_out;

    const int TB = 256;
    const int nodeBlocks = (NNODES + TB - 1) / TB;
    const int edgeBlocks = (NEDGES + TB - 1) / TB;
    const int elemBlocks = (NNODES * FEAT / 4 + TB - 1) / TB;
    const int warpBlocks = (NNODES * 32 + TB - 1) / TB;
    const int gemmBlocks = (NNODES + 127) / 128;
    const int wsplitBlocks = (128 * 64 + TB - 1) / TB;

    probe_kernel<<<1, 32>>>((const int*)ei, (const unsigned int*)drop0);

    // CSR build
    zero_counts_kernel<<<nodeBlocks, TB>>>();
    hist_kernel<<<edgeBlocks, TB>>>(ei);
    chunk_sum_kernel<<<NCHUNK, 256>>>();
    chunk_scan_kernel<<<1, 256>>>();
    rowptr_kernel<<<NCHUNK, 256>>>();
    fill_kernel<<<edgeBlocks, TB>>>(ei);

    // ---- layer 0 ----
    dropout_kernel<<<elemBlocks, TB>>>(x, drop0);
    wsplit_kernel<<<wsplitBlocks, TB>>>(Wrel0, Wroot0);
    aggregate_kernel<<<warpBlocks, TB>>>();
    gemm_mma_kernel<<<gemmBlocks, 256>>>(b0, drop1, nullptr, 1);

    // ---- layer 1 (z1 already in g_bufB) ----
    wsplit_kernel<<<wsplitBlocks, TB>>>(Wrel1, Wroot1);
    aggregate_kernel<<<warpBlocks, TB>>>();
    gemm_mma_kernel<<<gemmBlocks, 256>>>(b1, drop2, nullptr, 1);

    // ---- layer 2 ----
    wsplit_kernel<<<wsplitBlocks, TB>>>(Wrel2, Wroot2);
    aggregate_kernel<<<warpBlocks, TB>>>();
    gemm_mma_kernel<<<gemmBlocks, 256>>>(b2, nullptr, out, 0);
}